// round 2
// baseline (speedup 1.0000x reference)
#include <cuda_runtime.h>

#define SEQ   2048
#define NH    16
#define NB    2
#define HD    64
#define QBLK  64
#define KBLK  64
#define NKT   (SEQ / KBLK)

// Scratch for projected Q/K/V in [b,h,s,d] layout (16MB each)
__device__ float g_q[NB * NH * SEQ * HD];
__device__ float g_k[NB * NH * SEQ * HD];
__device__ float g_v[NB * NH * SEQ * HD];

// ---------------------------------------------------------------------------
// JAX threefry2x32, partitionable random_bits path:
//   key = (0, 42)  [jax.random.key(42)]
//   per flat element i: counts = (0, i); bits = x0_final ^ x1_final
// Key schedule: ks0=0, ks1=42, ks2 = 0 ^ 42 ^ 0x1BD11BDA = 0x1BD11BF0
// ---------------------------------------------------------------------------
__device__ __forceinline__ unsigned threefry_bits(unsigned c1)
{
    const unsigned K1 = 42u;
    const unsigned K2 = 0x1BD11BF0u;
    unsigned x0 = 0u;        // c0(=0) + ks0(=0)
    unsigned x1 = c1 + K1;   // c1 + ks1
#define TFR(r) { x0 += x1; x1 = __funnelshift_l(x1, x1, (r)); x1 ^= x0; }
    TFR(13); TFR(15); TFR(26); TFR(6);
    x0 += K1; x1 += K2 + 1u;
    TFR(17); TFR(29); TFR(16); TFR(24);
    x0 += K2; x1 += 2u;                // + ks0 + 2
    TFR(13); TFR(15); TFR(26); TFR(6);
    /* x0 += ks0 */ x1 += K1 + 3u;
    TFR(17); TFR(29); TFR(16); TFR(24);
    x0 += K1; x1 += K2 + 4u;
    TFR(13); TFR(15); TFR(26); TFR(6);
    x0 += K2; x1 += 5u;                // + ks0 + 5
#undef TFR
    return x0 ^ x1;
}

// ---------------------------------------------------------------------------
// Projection: out[b,h,s,e] = sum_d in[b,s,h,d] * W[e,d] + bias[e]
// gridDim.x = 65536/64 row-tiles, gridDim.y = 3 (q,k,v). 256 threads.
// ---------------------------------------------------------------------------
__global__ void __launch_bounds__(256) proj_kernel(
    const float* __restrict__ q_in, const float* __restrict__ k_in, const float* __restrict__ v_in,
    const float* __restrict__ Wq, const float* __restrict__ bq,
    const float* __restrict__ Wk, const float* __restrict__ bk,
    const float* __restrict__ Wv, const float* __restrict__ bv)
{
    __shared__ float Wt[64 * 68];   // d-major: Wt[d][e]
    __shared__ float It[64 * 68];   // d-major: It[d][row]
    __shared__ float bs[64];

    const int which = blockIdx.y;
    const float* in  = (which == 0) ? q_in : (which == 1) ? k_in : v_in;
    const float* W   = (which == 0) ? Wq  : (which == 1) ? Wk  : Wv;
    const float* bia = (which == 0) ? bq  : (which == 1) ? bk  : bv;
    float* outp      = (which == 0) ? g_q : (which == 1) ? g_k : g_v;

    const int tid = threadIdx.x;
    const int row0 = blockIdx.x * 64;

    if (tid < 64) bs[tid] = bia[tid];
    for (int i = tid; i < 1024; i += 256) {
        int r = i >> 4, c4 = (i & 15) << 2;
        float4 w = *(const float4*)(W + r * 64 + c4);
        Wt[(c4 + 0) * 68 + r] = w.x; Wt[(c4 + 1) * 68 + r] = w.y;
        Wt[(c4 + 2) * 68 + r] = w.z; Wt[(c4 + 3) * 68 + r] = w.w;
        float4 x = *(const float4*)(in + (size_t)(row0 + r) * 64 + c4);
        It[(c4 + 0) * 68 + r] = x.x; It[(c4 + 1) * 68 + r] = x.y;
        It[(c4 + 2) * 68 + r] = x.z; It[(c4 + 3) * 68 + r] = x.w;
    }
    __syncthreads();

    const int ty = tid >> 4, tx = tid & 15;
    float acc[4][4];
#pragma unroll
    for (int i = 0; i < 4; i++) { acc[i][0] = acc[i][1] = acc[i][2] = acc[i][3] = 0.0f; }

#pragma unroll 16
    for (int d = 0; d < 64; d++) {
        float4 a = *(const float4*)(It + d * 68 + 4 * ty);
        float4 w = *(const float4*)(Wt + d * 68 + 4 * tx);
        acc[0][0] += a.x * w.x; acc[0][1] += a.x * w.y; acc[0][2] += a.x * w.z; acc[0][3] += a.x * w.w;
        acc[1][0] += a.y * w.x; acc[1][1] += a.y * w.y; acc[1][2] += a.y * w.z; acc[1][3] += a.y * w.w;
        acc[2][0] += a.z * w.x; acc[2][1] += a.z * w.y; acc[2][2] += a.z * w.z; acc[2][3] += a.z * w.w;
        acc[3][0] += a.w * w.x; acc[3][1] += a.w * w.y; acc[3][2] += a.w * w.z; acc[3][3] += a.w * w.w;
    }

    float4 bb = *(const float4*)(bs + 4 * tx);
#pragma unroll
    for (int i = 0; i < 4; i++) {
        int r  = row0 + 4 * ty + i;     // r = ((b*2048 + s)*16 + h)
        int hh = r & 15;
        int ss = (r >> 4) & 2047;
        int bI = r >> 15;
        float4 res;
        res.x = acc[i][0] + bb.x; res.y = acc[i][1] + bb.y;
        res.z = acc[i][2] + bb.z; res.w = acc[i][3] + bb.w;
        *(float4*)(outp + ((size_t)((bI * NH + hh) * SEQ + ss)) * HD + 4 * tx) = res;
    }
}

// ---------------------------------------------------------------------------
// Flash attention with fused JAX-exact dropout.
// grid = (32 s-tiles, 16 heads, 2 batches), 256 threads (16x16, 4x4 tiles).
// ---------------------------------------------------------------------------
__global__ void __launch_bounds__(256) attn_kernel(const float* __restrict__ mask,
                                                   const float* __restrict__ inv_scale_p,
                                                   float* __restrict__ out)
{
    extern __shared__ float smem[];
    float* Qt   = smem;               // [64][68] d-major: Qt[d][row]
    float* KtPs = smem + 64 * 68;     // phase 1: Kt[d][col]; phase 2: Ps[t][row]
    float* Vs   = KtPs + 64 * 68;     // [64][64] natural: Vs[t][e]

    const int st = blockIdx.x, h = blockIdx.y, b = blockIdx.z;
    const int s0 = st * QBLK;
    const float* Qg = g_q + ((size_t)((b * NH + h) * SEQ + s0)) * HD;
    const float* Kg = g_k + ((size_t)((b * NH + h) * SEQ)) * HD;
    const float* Vg = g_v + ((size_t)((b * NH + h) * SEQ)) * HD;
    const float* Mg = mask + ((size_t)(b * SEQ + s0)) * SEQ;
    const float scale = 1.0f / inv_scale_p[0];

    const int tid = threadIdx.x;
    const int ty = tid >> 4, tx = tid & 15;

    // Load Q tile transposed (d-major)
    for (int i = tid; i < 1024; i += 256) {
        int r = i >> 4, c4 = (i & 15) << 2;
        float4 x = *(const float4*)(Qg + r * HD + c4);
        Qt[(c4 + 0) * 68 + r] = x.x; Qt[(c4 + 1) * 68 + r] = x.y;
        Qt[(c4 + 2) * 68 + r] = x.z; Qt[(c4 + 3) * 68 + r] = x.w;
    }

    float m_r[4], l_r[4], o[4][4];
#pragma unroll
    for (int i = 0; i < 4; i++) {
        m_r[i] = -3.0e38f; l_r[i] = 0.0f;
        o[i][0] = o[i][1] = o[i][2] = o[i][3] = 0.0f;
    }
    __syncthreads();

    // flat dropout index base: (((b*NH+h)*SEQ + s) * SEQ + t)
    const unsigned hs_base = (unsigned)((b * NH + h) * SEQ + s0);

    for (int kt = 0; kt < NKT; kt++) {
        const float* Kg_t = Kg + (size_t)kt * KBLK * HD;
        const float* Vg_t = Vg + (size_t)kt * KBLK * HD;
        for (int i = tid; i < 1024; i += 256) {
            int r = i >> 4, c4 = (i & 15) << 2;
            float4 kx = *(const float4*)(Kg_t + r * HD + c4);
            KtPs[(c4 + 0) * 68 + r] = kx.x; KtPs[(c4 + 1) * 68 + r] = kx.y;
            KtPs[(c4 + 2) * 68 + r] = kx.z; KtPs[(c4 + 3) * 68 + r] = kx.w;
            float4 vx = *(const float4*)(Vg_t + r * HD + c4);
            *(float4*)(Vs + r * 64 + c4) = vx;
        }
        __syncthreads();

        // ---- S = Q @ K^T ----
        float s[4][4];
#pragma unroll
        for (int i = 0; i < 4; i++) { s[i][0] = s[i][1] = s[i][2] = s[i][3] = 0.0f; }
#pragma unroll 16
        for (int d = 0; d < 64; d++) {
            float4 a  = *(const float4*)(Qt + d * 68 + 4 * ty);
            float4 kk = *(const float4*)(KtPs + d * 68 + 4 * tx);
            s[0][0] += a.x * kk.x; s[0][1] += a.x * kk.y; s[0][2] += a.x * kk.z; s[0][3] += a.x * kk.w;
            s[1][0] += a.y * kk.x; s[1][1] += a.y * kk.y; s[1][2] += a.y * kk.z; s[1][3] += a.y * kk.w;
            s[2][0] += a.z * kk.x; s[2][1] += a.z * kk.y; s[2][2] += a.z * kk.z; s[2][3] += a.z * kk.w;
            s[3][0] += a.w * kk.x; s[3][1] += a.w * kk.y; s[3][2] += a.w * kk.z; s[3][3] += a.w * kk.w;
        }
        __syncthreads();   // K-tile reads done; KtPs will be reused for P

        // ---- scale + mask + online softmax + dropout ----
        const int t0 = kt * KBLK;
#pragma unroll
        for (int i = 0; i < 4; i++) {
            float4 mv = *(const float4*)(Mg + (size_t)(4 * ty + i) * SEQ + t0 + 4 * tx);
            s[i][0] = fmaf(s[i][0], scale, mv.x);
            s[i][1] = fmaf(s[i][1], scale, mv.y);
            s[i][2] = fmaf(s[i][2], scale, mv.z);
            s[i][3] = fmaf(s[i][3], scale, mv.w);

            float mt = fmaxf(fmaxf(s[i][0], s[i][1]), fmaxf(s[i][2], s[i][3]));
            mt = fmaxf(mt, __shfl_xor_sync(0xffffffffu, mt, 1));
            mt = fmaxf(mt, __shfl_xor_sync(0xffffffffu, mt, 2));
            mt = fmaxf(mt, __shfl_xor_sync(0xffffffffu, mt, 4));
            mt = fmaxf(mt, __shfl_xor_sync(0xffffffffu, mt, 8));
            float mnew = fmaxf(m_r[i], mt);
            float cf   = __expf(m_r[i] - mnew);
            m_r[i] = mnew;

            unsigned idxbase = (hs_base + (unsigned)(4 * ty + i)) * (unsigned)SEQ
                             + (unsigned)(t0 + 4 * tx);
            float rs = 0.0f;
#pragma unroll
            for (int j = 0; j < 4; j++) {
                float p = __expf(s[i][j] - mnew);
                rs += p;                                   // normalizer uses PRE-dropout p
                unsigned bits = threefry_bits(idxbase + (unsigned)j);
                float u = __uint_as_float((bits >> 9) | 0x3f800000u) - 1.0f;
                s[i][j] = (u < 0.9f) ? p * (1.0f / 0.9f) : 0.0f;   // dropped, scaled p
            }
            rs += __shfl_xor_sync(0xffffffffu, rs, 1);
            rs += __shfl_xor_sync(0xffffffffu, rs, 2);
            rs += __shfl_xor_sync(0xffffffffu, rs, 4);
            rs += __shfl_xor_sync(0xffffffffu, rs, 8);
            l_r[i] = l_r[i] * cf + rs;
            o[i][0] *= cf; o[i][1] *= cf; o[i][2] *= cf; o[i][3] *= cf;
        }

        // write P transposed into KtPs: Ps[t][row]
#pragma unroll
        for (int i = 0; i < 4; i++) {
#pragma unroll
            for (int j = 0; j < 4; j++) {
                KtPs[(4 * tx + j) * 68 + 4 * ty + i] = s[i][j];
            }
        }
        __syncthreads();

        // ---- O += P @ V ----
#pragma unroll 16
        for (int t = 0; t < 64; t++) {
            float4 pp = *(const float4*)(KtPs + t * 68 + 4 * ty);
            float4 vv = *(const float4*)(Vs + t * 64 + 4 * tx);
            o[0][0] += pp.x * vv.x; o[0][1] += pp.x * vv.y; o[0][2] += pp.x * vv.z; o[0][3] += pp.x * vv.w;
            o[1][0] += pp.y * vv.x; o[1][1] += pp.y * vv.y; o[1][2] += pp.y * vv.z; o[1][3] += pp.y * vv.w;
            o[2][0] += pp.z * vv.x; o[2][1] += pp.z * vv.y; o[2][2] += pp.z * vv.z; o[2][3] += pp.z * vv.w;
            o[3][0] += pp.w * vv.x; o[3][1] += pp.w * vv.y; o[3][2] += pp.w * vv.z; o[3][3] += pp.w * vv.w;
        }
        __syncthreads();
    }

    // epilogue: normalize and store [b,h,s,e]
#pragma unroll
    for (int i = 0; i < 4; i++) {
        float invl = 1.0f / l_r[i];
        float4 r;
        r.x = o[i][0] * invl; r.y = o[i][1] * invl;
        r.z = o[i][2] * invl; r.w = o[i][3] * invl;
        *(float4*)(out + ((size_t)((b * NH + h) * SEQ + s0 + 4 * ty + i)) * HD + 4 * tx) = r;
    }
}

// ---------------------------------------------------------------------------
extern "C" void kernel_launch(void* const* d_in, const int* in_sizes, int n_in,
                              void* d_out, int out_size)
{
    const float* query = (const float*)d_in[0];
    const float* key_  = (const float*)d_in[1];
    const float* value = (const float*)d_in[2];
    const float* amask = (const float*)d_in[3];
    const float* invsc = (const float*)d_in[4];
    const float* Wq = (const float*)d_in[5];
    const float* bq = (const float*)d_in[6];
    const float* Wk = (const float*)d_in[7];
    const float* bk = (const float*)d_in[8];
    const float* Wv = (const float*)d_in[9];
    const float* bv = (const float*)d_in[10];
    float* out = (float*)d_out;

    (void)in_sizes; (void)n_in; (void)out_size;

    proj_kernel<<<dim3(1024, 3), 256>>>(query, key_, value, Wq, bq, Wk, bk, Wv, bv);

    constexpr int SMEM_BYTES = (64 * 68 + 64 * 68 + 64 * 64) * 4;   // 51200
    cudaFuncSetAttribute(attn_kernel, cudaFuncAttributeMaxDynamicSharedMemorySize, SMEM_BYTES);
    attn_kernel<<<dim3(NKT, NH, NB), 256, SMEM_BYTES>>>(amask, invsc, out);
}